// round 13
// baseline (speedup 1.0000x reference)
#include <cuda_runtime.h>
#include <cuda_fp16.h>
#include <cstdint>

#define BATCH  256
#define IN_DIM 14400
#define KNN    25
#define D0     7200
#define D1     3600
#define D2     1800

// ---------------- scratch (device globals: alloc-free) ----------------
__device__ __align__(16) __half g_xT[2 * IN_DIM * BATCH];  // (28800,256) fp16
__device__ __align__(16) __half g_a0[2 * D0 * BATCH];
__device__ __align__(16) __half g_a1[2 * D1 * BATCH];
__device__ __align__(16) float  g_h[2][BATCH][2];          // fused-fc accumulator

// ------- transpose one (channel, batch-half) quadrant; optionally zero g_h
// tile: 64 batch x 64 dims; grid (IN_DIM/64 = 225, 2)
__global__ __launch_bounds__(256)
void transpose_kernel(const float* __restrict__ x, const int ch, const int bh,
                      const int zf)
{
    __shared__ float s[64][68];
    const int t = threadIdx.x;

    if (zf && blockIdx.x == 0 && blockIdx.y == 0) {
        ((float4*)g_h)[t] = make_float4(0.f, 0.f, 0.f, 0.f);  // 256 float4 = all of g_h
    }

    const int dbase = ch * IN_DIM + blockIdx.x * 64;   // col in x == row in g_xT
    const int bbase = bh * 128 + blockIdx.y * 64;

    const int fc = t & 15;                 // float4 col within 64-dim tile
    const int r  = t >> 4;                 // 0..15
    const float4* __restrict__ x4 = (const float4*)x;
#pragma unroll
    for (int rr = 0; rr < 4; ++rr) {
        const int row = rr * 16 + r;       // batch row within tile
        float4 v = x4[(size_t)(bbase + row) * (2 * IN_DIM / 4) + (dbase >> 2) + fc];
        *(float4*)&s[row][fc * 4] = v;
    }
    __syncthreads();

    const int d  = t & 63;
    const int h0 = t >> 6;                 // 0..3
    uint4* __restrict__ o4 = (uint4*)g_xT;
#pragma unroll
    for (int hh = 0; hh < 2; ++hh) {
        const int h  = h0 + hh * 4;        // 0..7 (8 uint4 = 64 batch)
        const int b0 = h * 8;
        __half2 p0 = __floats2half2_rn(s[b0 + 0][d], s[b0 + 1][d]);
        __half2 p1 = __floats2half2_rn(s[b0 + 2][d], s[b0 + 3][d]);
        __half2 p2 = __floats2half2_rn(s[b0 + 4][d], s[b0 + 5][d]);
        __half2 p3 = __floats2half2_rn(s[b0 + 6][d], s[b0 + 7][d]);
        uint4 o;
        o.x = *(uint32_t*)&p0; o.y = *(uint32_t*)&p1;
        o.z = *(uint32_t*)&p2; o.w = *(uint32_t*)&p3;
        o4[(((size_t)(dbase + d)) * BATCH + bbase + b0) >> 3] = o;
    }
}

// ---------------- LCN layer, one channel x one batch-half --------------
// 128 threads = 8 d's x 16 lanes (lane = 8 batch elems via uint4).
// LAYER==2: fc head fused into epilogue (atomics into g_h).
template <int LAYER>
__global__ __launch_bounds__(128, 6)
void lcn_layer_kernel(const int* __restrict__ knn,
                      const float* __restrict__ w, const float* __restrict__ bias,
                      const float* __restrict__ fcw,
                      const int ch, const int bh)
{
    constexpr int PREV = (LAYER == 0) ? IN_DIM : (LAYER == 1 ? D0 : D1);
    constexpr int DIM  = (LAYER == 0) ? D0     : (LAYER == 1 ? D1 : D2);
    const __half* __restrict__ in  = (LAYER == 0) ? g_xT : (LAYER == 1 ? g_a0 : g_a1);
    __half*       __restrict__ out = (LAYER == 0) ? g_a0 : g_a1;

    const int d0 = blockIdx.x * 8;

    __shared__ int   s_off[8][KNN];
    __shared__ float s_w[8][KNN];

    const int t = threadIdx.x;
    for (int i = t; i < 8 * KNN; i += 128) {
        const int sub = i / KNN, k = i % KNN;
        const int d = d0 + sub;
        s_off[sub][k] = (knn[d * KNN + k] + ch * PREV) * (BATCH / 8) + bh * 16;
        s_w[sub][k]   = w[d * KNN + k];
    }
    __syncthreads();

    const int sub  = t >> 4;                 // which d (0..7)
    const int lane = t & 15;                 // uint4 lane over 128-batch half
    const int d    = d0 + sub;

    const uint4* __restrict__ in4 = (const uint4*)in;

    uint4 v0 = in4[s_off[sub][0] + lane];
    uint4 v1 = in4[s_off[sub][1] + lane];
    uint4 v2 = in4[s_off[sub][2] + lane];
    uint4 v3 = in4[s_off[sub][3] + lane];
    uint4 v4 = in4[s_off[sub][4] + lane];
    uint4 v5 = in4[s_off[sub][5] + lane];
    uint4 v6 = in4[s_off[sub][6] + lane];
    uint4 v7 = in4[s_off[sub][7] + lane];

    float a0 = 0.f, a1 = 0.f, a2 = 0.f, a3 = 0.f;
    float a4 = 0.f, a5 = 0.f, a6 = 0.f, a7 = 0.f;

#define LCN_FMA(V, KK)                                                     \
    {                                                                      \
        const float wv = s_w[sub][KK];                                     \
        float2 f0 = __half22float2(*(const __half2*)&(V).x);               \
        float2 f1 = __half22float2(*(const __half2*)&(V).y);               \
        float2 f2 = __half22float2(*(const __half2*)&(V).z);               \
        float2 f3 = __half22float2(*(const __half2*)&(V).w);               \
        a0 += wv * f0.x; a1 += wv * f0.y;                                  \
        a2 += wv * f1.x; a3 += wv * f1.y;                                  \
        a4 += wv * f2.x; a5 += wv * f2.y;                                  \
        a6 += wv * f3.x; a7 += wv * f3.y;                                  \
    }
#define LCN_STEP(V, KK)                                                    \
    {                                                                      \
        uint4 nv = in4[s_off[sub][(KK) + 8] + lane];                       \
        LCN_FMA(V, KK);                                                    \
        V = nv;                                                            \
    }

    LCN_STEP(v0, 0)  LCN_STEP(v1, 1)  LCN_STEP(v2, 2)  LCN_STEP(v3, 3)
    LCN_STEP(v4, 4)  LCN_STEP(v5, 5)  LCN_STEP(v6, 6)  LCN_STEP(v7, 7)
    LCN_STEP(v0, 8)  LCN_STEP(v1, 9)  LCN_STEP(v2, 10) LCN_STEP(v3, 11)
    LCN_STEP(v4, 12) LCN_STEP(v5, 13) LCN_STEP(v6, 14) LCN_STEP(v7, 15)
    LCN_STEP(v0, 16)
    LCN_FMA(v1, 17)  LCN_FMA(v2, 18)  LCN_FMA(v3, 19)  LCN_FMA(v4, 20)
    LCN_FMA(v5, 21)  LCN_FMA(v6, 22)  LCN_FMA(v7, 23)  LCN_FMA(v0, 24)
#undef LCN_STEP
#undef LCN_FMA

    const float bv = bias[d];
    a0 = fmaxf(a0 + bv, 0.f); a1 = fmaxf(a1 + bv, 0.f);
    a2 = fmaxf(a2 + bv, 0.f); a3 = fmaxf(a3 + bv, 0.f);
    a4 = fmaxf(a4 + bv, 0.f); a5 = fmaxf(a5 + bv, 0.f);
    a6 = fmaxf(a6 + bv, 0.f); a7 = fmaxf(a7 + bv, 0.f);

    if constexpr (LAYER < 2) {
        __half2 p0 = __floats2half2_rn(a0, a1);
        __half2 p1 = __floats2half2_rn(a2, a3);
        __half2 p2 = __floats2half2_rn(a4, a5);
        __half2 p3 = __floats2half2_rn(a6, a7);
        uint4 o;
        o.x = *(uint32_t*)&p0; o.y = *(uint32_t*)&p1;
        o.z = *(uint32_t*)&p2; o.w = *(uint32_t*)&p3;
        ((uint4*)out)[(size_t)(ch * DIM + d) * (BATCH / 8) + bh * 16 + lane] = o;
    } else {
        // fused FC head: h[ch][b][o] += a(d,b) * fcw[o*D2 + d]
        __shared__ float s_fc[8][16][8][2];  // [sub][lane][j][o]  8KB
        const float fw0 = fcw[d];
        const float fw1 = fcw[D2 + d];
        float av[8] = { a0, a1, a2, a3, a4, a5, a6, a7 };
#pragma unroll
        for (int j = 0; j < 8; ++j) {
            s_fc[sub][lane][j][0] = av[j] * fw0;
            s_fc[sub][lane][j][1] = av[j] * fw1;
        }
        __syncthreads();
        // 256 (b_local, o) pairs; each thread reduces 2 pairs over 8 subs
#pragma unroll
        for (int pp = 0; pp < 2; ++pp) {
            const int p = t + pp * 128;
            const int bl = p >> 1;            // 0..127
            const int o  = p & 1;
            const int ln = bl >> 3;
            const int j  = bl & 7;
            float s = 0.f;
#pragma unroll
            for (int su = 0; su < 8; ++su) s += s_fc[su][ln][j][o];
            atomicAdd(&g_h[ch][bh * 128 + bl][o], s);
        }
    }
}

// ---------------- final: relu(h)+bias, tiny fc3 ------------------------
__global__ void fc_final_kernel(const float* __restrict__ fcp_b,
                                const float* __restrict__ fcn_b,
                                const float* __restrict__ fc3_w,
                                const float* __restrict__ fc3_b,
                                float* __restrict__ out)
{
    const int b = threadIdx.x;
    float h0 = fcp_b[0] + g_h[0][b][0];
    float h1 = fcp_b[1] + g_h[0][b][1];
    float h2 = fcn_b[0] + g_h[1][b][0];
    float h3 = fcn_b[1] + g_h[1][b][1];
    h0 = fmaxf(h0, 0.f); h1 = fmaxf(h1, 0.f);
    h2 = fmaxf(h2, 0.f); h3 = fmaxf(h3, 0.f);
    out[b * 2 + 0] = fc3_b[0] + fc3_w[0] * h0 + fc3_w[1] * h1 + fc3_w[2] * h2 + fc3_w[3] * h3;
    out[b * 2 + 1] = fc3_b[1] + fc3_w[4] * h0 + fc3_w[5] * h1 + fc3_w[6] * h2 + fc3_w[7] * h3;
}

// ---------------- stream/event pool: created ONCE, reused every call ----
struct SyncPool {
    cudaStream_t s2, s3, s4;
    cudaEvent_t  e_tp0, e_tn0, e_tp1, e_c2, e_c3, e_c4;
    SyncPool() {
        cudaStreamCreateWithFlags(&s2, cudaStreamNonBlocking);
        cudaStreamCreateWithFlags(&s3, cudaStreamNonBlocking);
        cudaStreamCreateWithFlags(&s4, cudaStreamNonBlocking);
        cudaEventCreateWithFlags(&e_tp0, cudaEventDisableTiming);
        cudaEventCreateWithFlags(&e_tn0, cudaEventDisableTiming);
        cudaEventCreateWithFlags(&e_tp1, cudaEventDisableTiming);
        cudaEventCreateWithFlags(&e_c2, cudaEventDisableTiming);
        cudaEventCreateWithFlags(&e_c3, cudaEventDisableTiming);
        cudaEventCreateWithFlags(&e_c4, cudaEventDisableTiming);
    }
};
static SyncPool& pool() { static SyncPool p; return p; }

// ---------------- launcher: 4 staggered chains on 4 streams ------------
extern "C" void kernel_launch(void* const* d_in, const int* in_sizes, int n_in,
                              void* d_out, int out_size)
{
    const float* x    = (const float*)d_in[0];
    const int*   knn0 = (const int*)d_in[1];
    const int*   knn1 = (const int*)d_in[2];
    const int*   knn2 = (const int*)d_in[3];
    const float* wp0 = (const float*)d_in[4];
    const float* bp0 = (const float*)d_in[5];
    const float* wp1 = (const float*)d_in[6];
    const float* bp1 = (const float*)d_in[7];
    const float* wp2 = (const float*)d_in[8];
    const float* bp2 = (const float*)d_in[9];
    const float* fcp_w = (const float*)d_in[10];
    const float* fcp_b = (const float*)d_in[11];
    const float* wn0 = (const float*)d_in[12];
    const float* bn0 = (const float*)d_in[13];
    const float* wn1 = (const float*)d_in[14];
    const float* bn1 = (const float*)d_in[15];
    const float* wn2 = (const float*)d_in[16];
    const float* bn2 = (const float*)d_in[17];
    const float* fcn_w = (const float*)d_in[18];
    const float* fcn_b = (const float*)d_in[19];
    const float* fc3_w = (const float*)d_in[20];
    const float* fc3_b = (const float*)d_in[21];
    float* out = (float*)d_out;

    SyncPool& P = pool();
    const dim3 tgrid(IN_DIM / 64, 2);

    // T(p,b0) on origin (also zeroes g_h); chain (p,b0) follows on origin
    transpose_kernel<<<tgrid, 256>>>(x, 0, 0, 1);
    cudaEventRecord(P.e_tp0, 0);
    lcn_layer_kernel<0><<<D0 / 8, 128>>>(knn0, wp0, bp0, nullptr, 0, 0);
    lcn_layer_kernel<1><<<D1 / 8, 128>>>(knn1, wp1, bp1, nullptr, 0, 0);
    lcn_layer_kernel<2><<<D2 / 8, 128>>>(knn2, wp2, bp2, fcp_w, 0, 0);

    // s3: T(n,b0) after T(p,b0); chain (n,b0)
    cudaStreamWaitEvent(P.s3, P.e_tp0, 0);
    transpose_kernel<<<tgrid, 256, 0, P.s3>>>(x, 1, 0, 0);
    cudaEventRecord(P.e_tn0, P.s3);
    lcn_layer_kernel<0><<<D0 / 8, 128, 0, P.s3>>>(knn0, wn0, bn0, nullptr, 1, 0);
    lcn_layer_kernel<1><<<D1 / 8, 128, 0, P.s3>>>(knn1, wn1, bn1, nullptr, 1, 0);
    lcn_layer_kernel<2><<<D2 / 8, 128, 0, P.s3>>>(knn2, wn2, bn2, fcn_w, 1, 0);
    cudaEventRecord(P.e_c3, P.s3);

    // s2: T(p,b1) after T(n,b0); chain (p,b1)
    cudaStreamWaitEvent(P.s2, P.e_tn0, 0);
    transpose_kernel<<<tgrid, 256, 0, P.s2>>>(x, 0, 1, 0);
    cudaEventRecord(P.e_tp1, P.s2);
    lcn_layer_kernel<0><<<D0 / 8, 128, 0, P.s2>>>(knn0, wp0, bp0, nullptr, 0, 1);
    lcn_layer_kernel<1><<<D1 / 8, 128, 0, P.s2>>>(knn1, wp1, bp1, nullptr, 0, 1);
    lcn_layer_kernel<2><<<D2 / 8, 128, 0, P.s2>>>(knn2, wp2, bp2, fcp_w, 0, 1);
    cudaEventRecord(P.e_c2, P.s2);

    // s4: T(n,b1) after T(p,b1); chain (n,b1)
    cudaStreamWaitEvent(P.s4, P.e_tp1, 0);
    transpose_kernel<<<tgrid, 256, 0, P.s4>>>(x, 1, 1, 0);
    lcn_layer_kernel<0><<<D0 / 8, 128, 0, P.s4>>>(knn0, wn0, bn0, nullptr, 1, 1);
    lcn_layer_kernel<1><<<D1 / 8, 128, 0, P.s4>>>(knn1, wn1, bn1, nullptr, 1, 1);
    lcn_layer_kernel<2><<<D2 / 8, 128, 0, P.s4>>>(knn2, wn2, bn2, fcn_w, 1, 1);
    cudaEventRecord(P.e_c4, P.s4);

    // join all chains into origin; final tiny kernel
    cudaStreamWaitEvent(0, P.e_c2, 0);
    cudaStreamWaitEvent(0, P.e_c3, 0);
    cudaStreamWaitEvent(0, P.e_c4, 0);
    fc_final_kernel<<<1, 256>>>(fcp_b, fcn_b, fc3_w, fc3_b, out);
}

// round 14
// speedup vs baseline: 1.3839x; 1.3839x over previous
#include <cuda_runtime.h>
#include <cuda_fp16.h>
#include <cstdint>

#define BATCH  256
#define IN_DIM 14400
#define KNN    25
#define D0     7200
#define D1     3600
#define D2     1800

// ---------------- scratch (device globals: alloc-free) ----------------
__device__ __align__(16) __half g_xT[2 * IN_DIM * BATCH];  // (28800,256) fp16
__device__ __align__(16) __half g_a0[2 * D0 * BATCH];
__device__ __align__(16) __half g_a1[2 * D1 * BATCH];
__device__ __align__(16) float  g_h[2][BATCH][2];          // fused-fc accumulator

// ---------------- transpose (one batch half): x (256,28800) fp32 -> g_xT fp16
// zf: block (0,0) also zeroes g_h (safe: all layer2 kernels are ordered after)
__global__ __launch_bounds__(256)
void transpose_kernel(const float* __restrict__ x, const int bh, const int zf) {
    __shared__ float s[32][132];
    const int t = threadIdx.x;

    if (zf && blockIdx.x == 0 && blockIdx.y == 0) {
        ((float4*)g_h)[t] = make_float4(0.f, 0.f, 0.f, 0.f);  // 256 float4 = all of g_h
    }

    const int dbase = blockIdx.x * 128;
    const int bbase = bh * 128 + blockIdx.y * 32;

    const int fc = t & 31;
    const int r  = t >> 5;
    const float4* __restrict__ x4 = (const float4*)x;
#pragma unroll
    for (int rr = 0; rr < 4; ++rr) {
        const int row = rr * 8 + r;
        float4 v = x4[(size_t)(bbase + row) * (2 * IN_DIM / 4) + (dbase / 4) + fc];
        *(float4*)&s[row][fc * 4] = v;
    }
    __syncthreads();

    const int d = t & 127;
    const int h = t >> 7;
    uint4* __restrict__ o4 = (uint4*)g_xT;
#pragma unroll
    for (int hh = 0; hh < 2; ++hh) {
        const int q  = hh * 2 + h;
        const int b0 = q * 8;
        __half2 p0 = __floats2half2_rn(s[b0 + 0][d], s[b0 + 1][d]);
        __half2 p1 = __floats2half2_rn(s[b0 + 2][d], s[b0 + 3][d]);
        __half2 p2 = __floats2half2_rn(s[b0 + 4][d], s[b0 + 5][d]);
        __half2 p3 = __floats2half2_rn(s[b0 + 6][d], s[b0 + 7][d]);
        uint4 o;
        o.x = *(uint32_t*)&p0; o.y = *(uint32_t*)&p1;
        o.z = *(uint32_t*)&p2; o.w = *(uint32_t*)&p3;
        o4[(((size_t)(dbase + d)) * BATCH + bbase + b0) >> 3] = o;
    }
}

// ---------------- LCN layer, one channel x one batch-half --------------
// 128 threads = 8 d's x 16 lanes (lane = 8 batch elems via uint4).
// LAYER==2: fc head fused into epilogue (atomics into g_h).
template <int LAYER>
__global__ __launch_bounds__(128, 6)
void lcn_layer_kernel(const int* __restrict__ knn,
                      const float* __restrict__ w, const float* __restrict__ bias,
                      const float* __restrict__ fcw,
                      const int ch, const int bh)
{
    constexpr int PREV = (LAYER == 0) ? IN_DIM : (LAYER == 1 ? D0 : D1);
    constexpr int DIM  = (LAYER == 0) ? D0     : (LAYER == 1 ? D1 : D2);
    const __half* __restrict__ in  = (LAYER == 0) ? g_xT : (LAYER == 1 ? g_a0 : g_a1);
    __half*       __restrict__ out = (LAYER == 0) ? g_a0 : g_a1;

    const int d0 = blockIdx.x * 8;

    __shared__ int   s_off[8][KNN];
    __shared__ float s_w[8][KNN];

    const int t = threadIdx.x;
    for (int i = t; i < 8 * KNN; i += 128) {
        const int sub = i / KNN, k = i % KNN;
        const int d = d0 + sub;
        s_off[sub][k] = (knn[d * KNN + k] + ch * PREV) * (BATCH / 8) + bh * 16;
        s_w[sub][k]   = w[d * KNN + k];
    }
    __syncthreads();

    const int sub  = t >> 4;                 // which d (0..7)
    const int lane = t & 15;                 // uint4 lane over 128-batch half
    const int d    = d0 + sub;

    const uint4* __restrict__ in4 = (const uint4*)in;

    uint4 v0 = in4[s_off[sub][0] + lane];
    uint4 v1 = in4[s_off[sub][1] + lane];
    uint4 v2 = in4[s_off[sub][2] + lane];
    uint4 v3 = in4[s_off[sub][3] + lane];
    uint4 v4 = in4[s_off[sub][4] + lane];
    uint4 v5 = in4[s_off[sub][5] + lane];
    uint4 v6 = in4[s_off[sub][6] + lane];
    uint4 v7 = in4[s_off[sub][7] + lane];

    float a0 = 0.f, a1 = 0.f, a2 = 0.f, a3 = 0.f;
    float a4 = 0.f, a5 = 0.f, a6 = 0.f, a7 = 0.f;

#define LCN_FMA(V, KK)                                                     \
    {                                                                      \
        const float wv = s_w[sub][KK];                                     \
        float2 f0 = __half22float2(*(const __half2*)&(V).x);               \
        float2 f1 = __half22float2(*(const __half2*)&(V).y);               \
        float2 f2 = __half22float2(*(const __half2*)&(V).z);               \
        float2 f3 = __half22float2(*(const __half2*)&(V).w);               \
        a0 += wv * f0.x; a1 += wv * f0.y;                                  \
        a2 += wv * f1.x; a3 += wv * f1.y;                                  \
        a4 += wv * f2.x; a5 += wv * f2.y;                                  \
        a6 += wv * f3.x; a7 += wv * f3.y;                                  \
    }
#define LCN_STEP(V, KK)                                                    \
    {                                                                      \
        uint4 nv = in4[s_off[sub][(KK) + 8] + lane];                       \
        LCN_FMA(V, KK);                                                    \
        V = nv;                                                            \
    }

    LCN_STEP(v0, 0)  LCN_STEP(v1, 1)  LCN_STEP(v2, 2)  LCN_STEP(v3, 3)
    LCN_STEP(v4, 4)  LCN_STEP(v5, 5)  LCN_STEP(v6, 6)  LCN_STEP(v7, 7)
    LCN_STEP(v0, 8)  LCN_STEP(v1, 9)  LCN_STEP(v2, 10) LCN_STEP(v3, 11)
    LCN_STEP(v4, 12) LCN_STEP(v5, 13) LCN_STEP(v6, 14) LCN_STEP(v7, 15)
    LCN_STEP(v0, 16)
    LCN_FMA(v1, 17)  LCN_FMA(v2, 18)  LCN_FMA(v3, 19)  LCN_FMA(v4, 20)
    LCN_FMA(v5, 21)  LCN_FMA(v6, 22)  LCN_FMA(v7, 23)  LCN_FMA(v0, 24)
#undef LCN_STEP
#undef LCN_FMA

    const float bv = bias[d];
    a0 = fmaxf(a0 + bv, 0.f); a1 = fmaxf(a1 + bv, 0.f);
    a2 = fmaxf(a2 + bv, 0.f); a3 = fmaxf(a3 + bv, 0.f);
    a4 = fmaxf(a4 + bv, 0.f); a5 = fmaxf(a5 + bv, 0.f);
    a6 = fmaxf(a6 + bv, 0.f); a7 = fmaxf(a7 + bv, 0.f);

    if constexpr (LAYER < 2) {
        __half2 p0 = __floats2half2_rn(a0, a1);
        __half2 p1 = __floats2half2_rn(a2, a3);
        __half2 p2 = __floats2half2_rn(a4, a5);
        __half2 p3 = __floats2half2_rn(a6, a7);
        uint4 o;
        o.x = *(uint32_t*)&p0; o.y = *(uint32_t*)&p1;
        o.z = *(uint32_t*)&p2; o.w = *(uint32_t*)&p3;
        ((uint4*)out)[(size_t)(ch * DIM + d) * (BATCH / 8) + bh * 16 + lane] = o;
    } else {
        // fused FC head: h[ch][b][o] += a(d,b) * fcw[o*D2 + d]
        __shared__ float s_fc[8][16][8][2];  // [sub][lane][j][o]  8KB
        const float fw0 = fcw[d];
        const float fw1 = fcw[D2 + d];
        float av[8] = { a0, a1, a2, a3, a4, a5, a6, a7 };
#pragma unroll
        for (int j = 0; j < 8; ++j) {
            s_fc[sub][lane][j][0] = av[j] * fw0;
            s_fc[sub][lane][j][1] = av[j] * fw1;
        }
        __syncthreads();
        // 256 (b_local, o) pairs; each thread reduces 2 pairs over 8 subs
#pragma unroll
        for (int pp = 0; pp < 2; ++pp) {
            const int p = t + pp * 128;
            const int bl = p >> 1;            // 0..127
            const int o  = p & 1;
            const int ln = bl >> 3;
            const int j  = bl & 7;
            float s = 0.f;
#pragma unroll
            for (int su = 0; su < 8; ++su) s += s_fc[su][ln][j][o];
            atomicAdd(&g_h[ch][bh * 128 + bl][o], s);
        }
    }
}

// ---------------- final: relu(h)+bias, tiny fc3 ------------------------
__global__ void fc_final_kernel(const float* __restrict__ fcp_b,
                                const float* __restrict__ fcn_b,
                                const float* __restrict__ fc3_w,
                                const float* __restrict__ fc3_b,
                                float* __restrict__ out)
{
    const int b = threadIdx.x;
    float h0 = fcp_b[0] + g_h[0][b][0];
    float h1 = fcp_b[1] + g_h[0][b][1];
    float h2 = fcn_b[0] + g_h[1][b][0];
    float h3 = fcn_b[1] + g_h[1][b][1];
    h0 = fmaxf(h0, 0.f); h1 = fmaxf(h1, 0.f);
    h2 = fmaxf(h2, 0.f); h3 = fmaxf(h3, 0.f);
    out[b * 2 + 0] = fc3_b[0] + fc3_w[0] * h0 + fc3_w[1] * h1 + fc3_w[2] * h2 + fc3_w[3] * h3;
    out[b * 2 + 1] = fc3_b[1] + fc3_w[4] * h0 + fc3_w[5] * h1 + fc3_w[6] * h2 + fc3_w[7] * h3;
}

// ---------------- stream/event pool: created ONCE, reused every call ----
struct SyncPool {
    cudaStream_t s2, s3, s4;
    cudaEvent_t  e_t0, e_t1, e_c2, e_c3, e_c4;
    SyncPool() {
        cudaStreamCreateWithFlags(&s2, cudaStreamNonBlocking);
        cudaStreamCreateWithFlags(&s3, cudaStreamNonBlocking);
        cudaStreamCreateWithFlags(&s4, cudaStreamNonBlocking);
        cudaEventCreateWithFlags(&e_t0, cudaEventDisableTiming);
        cudaEventCreateWithFlags(&e_t1, cudaEventDisableTiming);
        cudaEventCreateWithFlags(&e_c2, cudaEventDisableTiming);
        cudaEventCreateWithFlags(&e_c3, cudaEventDisableTiming);
        cudaEventCreateWithFlags(&e_c4, cudaEventDisableTiming);
    }
};
static SyncPool& pool() { static SyncPool p; return p; }

// ---------------- launcher: R10 topology, zero_h folded into T(b0) -----
extern "C" void kernel_launch(void* const* d_in, const int* in_sizes, int n_in,
                              void* d_out, int out_size)
{
    const float* x    = (const float*)d_in[0];
    const int*   knn0 = (const int*)d_in[1];
    const int*   knn1 = (const int*)d_in[2];
    const int*   knn2 = (const int*)d_in[3];
    const float* wp0 = (const float*)d_in[4];
    const float* bp0 = (const float*)d_in[5];
    const float* wp1 = (const float*)d_in[6];
    const float* bp1 = (const float*)d_in[7];
    const float* wp2 = (const float*)d_in[8];
    const float* bp2 = (const float*)d_in[9];
    const float* fcp_w = (const float*)d_in[10];
    const float* fcp_b = (const float*)d_in[11];
    const float* wn0 = (const float*)d_in[12];
    const float* bn0 = (const float*)d_in[13];
    const float* wn1 = (const float*)d_in[14];
    const float* bn1 = (const float*)d_in[15];
    const float* wn2 = (const float*)d_in[16];
    const float* bn2 = (const float*)d_in[17];
    const float* fcn_w = (const float*)d_in[18];
    const float* fcn_b = (const float*)d_in[19];
    const float* fc3_w = (const float*)d_in[20];
    const float* fc3_b = (const float*)d_in[21];
    float* out = (float*)d_out;

    SyncPool& P = pool();

    // transpose batch-half 0 on default stream (block 0 zeroes g_h)
    transpose_kernel<<<dim3((2 * IN_DIM) / 128, 4), 256>>>(x, 0, 1);
    cudaEventRecord(P.e_t0, 0);

    // transpose batch-half 1 on s2, after t0 (deliberate stagger)
    cudaStreamWaitEvent(P.s2, P.e_t0, 0);
    transpose_kernel<<<dim3((2 * IN_DIM) / 128, 4), 256, 0, P.s2>>>(x, 1, 0);
    cudaEventRecord(P.e_t1, P.s2);

    // chain (p, b0) on default stream
    lcn_layer_kernel<0><<<D0 / 8, 128>>>(knn0, wp0, bp0, nullptr, 0, 0);
    lcn_layer_kernel<1><<<D1 / 8, 128>>>(knn1, wp1, bp1, nullptr, 0, 0);
    lcn_layer_kernel<2><<<D2 / 8, 128>>>(knn2, wp2, bp2, fcp_w, 0, 0);

    // chain (n, b0) on s3
    cudaStreamWaitEvent(P.s3, P.e_t0, 0);
    lcn_layer_kernel<0><<<D0 / 8, 128, 0, P.s3>>>(knn0, wn0, bn0, nullptr, 1, 0);
    lcn_layer_kernel<1><<<D1 / 8, 128, 0, P.s3>>>(knn1, wn1, bn1, nullptr, 1, 0);
    lcn_layer_kernel<2><<<D2 / 8, 128, 0, P.s3>>>(knn2, wn2, bn2, fcn_w, 1, 0);
    cudaEventRecord(P.e_c3, P.s3);

    // chain (p, b1) on s2 (ordered after transpose b1)
    lcn_layer_kernel<0><<<D0 / 8, 128, 0, P.s2>>>(knn0, wp0, bp0, nullptr, 0, 1);
    lcn_layer_kernel<1><<<D1 / 8, 128, 0, P.s2>>>(knn1, wp1, bp1, nullptr, 0, 1);
    lcn_layer_kernel<2><<<D2 / 8, 128, 0, P.s2>>>(knn2, wp2, bp2, fcp_w, 0, 1);
    cudaEventRecord(P.e_c2, P.s2);

    // chain (n, b1) on s4
    cudaStreamWaitEvent(P.s4, P.e_t1, 0);
    lcn_layer_kernel<0><<<D0 / 8, 128, 0, P.s4>>>(knn0, wn0, bn0, nullptr, 1, 1);
    lcn_layer_kernel<1><<<D1 / 8, 128, 0, P.s4>>>(knn1, wn1, bn1, nullptr, 1, 1);
    lcn_layer_kernel<2><<<D2 / 8, 128, 0, P.s4>>>(knn2, wn2, bn2, fcn_w, 1, 1);
    cudaEventRecord(P.e_c4, P.s4);

    // join all chains into origin; final tiny kernel
    cudaStreamWaitEvent(0, P.e_c2, 0);
    cudaStreamWaitEvent(0, P.e_c3, 0);
    cudaStreamWaitEvent(0, P.e_c4, 0);
    fc_final_kernel<<<1, 256>>>(fcp_b, fcn_b, fc3_w, fc3_b, out);
}